// round 7
// baseline (speedup 1.0000x reference)
#include <cuda_runtime.h>

// BinaryMaskEdgeSmoothing, R7: prefetch-distance-2 register pipeline.
//
// Binary inputs => sum9 (3x3 box) and gsum (16*gauss) are exact small ints in
// f32. Verified-equivalent rule (rel_err = 0.0 since R4):
//     out = (gsum >= 9) || (gsum == 8 && cen == 1 && sum9 >= 4)
// via: qual = 6*cen + sum9; adj = qual>9.5 ? 0.6 : 0; out = gsum+adj > 8.5.
//
// Memory: 8 cols/thread register-rolling strips, 2 rows/iter, shuffle-based
// halo (lanes 0/31 load single boundary scalars). NEW: two row-pairs pending
// (8 LDG.128 = 2KB per warp in flight) -- the pair converted each iteration
// was issued TWO iterations ago. At 16 warps/SM (bounds 128,4) that is 32KB
// in-flight per SM, past the DRAM saturation knee that capped R6 at 72%.

#define IMG_W 1024
#define IMG_H 1024
#define RPB   32              // rows per block
#define THREADS (IMG_W / 8)   // 128: block spans full row width

struct RawV { float4 a, b; float bl, br; };   // 8 owned cols + boundary scalars
struct Sums { float t[8]; float g[8]; };      // 1,1,1 and 1,2,1 horizontal sums

__device__ __forceinline__ RawV issue_raw(const float* __restrict__ p,
                                          bool ld_l, bool ld_r, bool valid) {
    RawV r;
    if (valid) {
        r.a  = *reinterpret_cast<const float4*>(p);        // 16B-aligned
        r.b  = *reinterpret_cast<const float4*>(p + 4);
        r.bl = ld_l ? p[-1] : 0.f;   // lane 0 only: single-line load
        r.br = ld_r ? p[8]  : 0.f;   // lane 31 only
    } else {
        r.a = make_float4(0.f, 0.f, 0.f, 0.f);
        r.b = r.a; r.bl = 0.f; r.br = 0.f;
    }
    return r;
}

__device__ __forceinline__ Sums make_sums(const RawV& r, int lane) {
    // Left halo = lane-1's e[8] (= b.w); right halo = lane+1's e[1] (= a.x).
    float e0 = __shfl_up_sync(0xFFFFFFFFu, r.b.w, 1);
    float e9 = __shfl_down_sync(0xFFFFFFFFu, r.a.x, 1);
    if (lane == 0)  e0 = r.bl;
    if (lane == 31) e9 = r.br;

    float e[10] = {e0, r.a.x, r.a.y, r.a.z, r.a.w,
                   r.b.x, r.b.y, r.b.z, r.b.w, e9};
    Sums s;
    #pragma unroll
    for (int j = 0; j < 8; ++j) {
        s.t[j] = e[j] + e[j + 1] + e[j + 2];
        s.g[j] = s.t[j] + e[j + 1];
    }
    return s;
}

__device__ __forceinline__ void compute_row(const Sums& A, const Sums& B,
                                            const Sums& C, float* __restrict__ res) {
    #pragma unroll
    for (int j = 0; j < 8; ++j) {
        float sum9 = A.t[j] + B.t[j] + C.t[j];            // 0..9 exact
        float t1   = A.g[j] + C.g[j];
        float gsum = fmaf(2.f, B.g[j], t1);               // 0..16 exact
        float cen  = B.g[j] - B.t[j];                     // 0 or 1
        float qual = fmaf(6.f, cen, sum9);                // >=10 <=> lo-qualify
        float adj  = (qual > 9.5f) ? 0.6f : 0.f;
        res[j] = (gsum + adj > 8.5f) ? 1.f : 0.f;
    }
}

__device__ __forceinline__ void store_row(float* __restrict__ p,
                                          const float* __restrict__ res) {
    *reinterpret_cast<float4*>(p)     = make_float4(res[0], res[1], res[2], res[3]);
    *reinterpret_cast<float4*>(p + 4) = make_float4(res[4], res[5], res[6], res[7]);
}

__global__ void __launch_bounds__(THREADS, 4)
edge_smooth_kernel(const float* __restrict__ in, float* __restrict__ out) {
    const int img  = blockIdx.y;                 // 0..B*C-1
    const int r0   = blockIdx.x * RPB;
    const int x0   = threadIdx.x * 8;
    const int lane = threadIdx.x & 31;

    const float* ib = in  + (size_t)img * IMG_H * IMG_W + x0;
    float*       ob = out + (size_t)img * IMG_H * IMG_W + x0;

    const bool ld_l = (lane == 0)  && (x0 > 0);
    const bool ld_r = (lane == 31) && (x0 + 8 < IMG_W);
    const int  hi_row = min(r0 + RPB + 1, IMG_H);   // last row this strip reads

    // Prime: sums for rows r0-1, r0; TWO row-pairs in flight.
    Sums A = make_sums(issue_raw(ib + (size_t)(r0 - 1) * IMG_W, ld_l, ld_r, r0 > 0), lane);
    Sums B = make_sums(issue_raw(ib + (size_t)r0 * IMG_W,       ld_l, ld_r, true),  lane);
    RawV p0a = issue_raw(ib + (size_t)(r0 + 1) * IMG_W, ld_l, ld_r, (r0 + 1) < hi_row);
    RawV p0b = issue_raw(ib + (size_t)(r0 + 2) * IMG_W, ld_l, ld_r, (r0 + 2) < hi_row);
    RawV p1a = issue_raw(ib + (size_t)(r0 + 3) * IMG_W, ld_l, ld_r, (r0 + 3) < hi_row);
    RawV p1b = issue_raw(ib + (size_t)(r0 + 4) * IMG_W, ld_l, ld_r, (r0 + 4) < hi_row);

    const float* pin = ib + (size_t)(r0 + 5) * IMG_W;   // next prefetch row
    float*       po  = ob + (size_t)r0 * IMG_W;         // next store row

    #pragma unroll 4
    for (int y = r0; y < r0 + RPB; y += 2) {
        // Issue pair for iteration i+2 before consuming pair from i-2.
        RawV p2a = issue_raw(pin,         ld_l, ld_r, (y + 5) < hi_row);
        RawV p2b = issue_raw(pin + IMG_W, ld_l, ld_r, (y + 6) < hi_row);
        pin += 2 * IMG_W;

        Sums C = make_sums(p0a, lane);
        Sums D = make_sums(p0b, lane);

        float res0[8], res1[8];
        compute_row(A, B, C, res0);
        compute_row(B, C, D, res1);
        store_row(po,         res0);
        store_row(po + IMG_W, res1);
        po += 2 * IMG_W;

        A = C; B = D;
        p0a = p1a; p0b = p1b;
        p1a = p2a; p1b = p2b;
    }
}

extern "C" void kernel_launch(void* const* d_in, const int* in_sizes, int n_in,
                              void* d_out, int out_size) {
    const float* mask = (const float*)d_in[0];   // (B,C,1024,1024) f32
    float*       out  = (float*)d_out;

    int n_imgs = in_sizes[0] / (IMG_H * IMG_W);  // B*C

    dim3 grid(IMG_H / RPB, n_imgs);
    dim3 block(THREADS);
    edge_smooth_kernel<<<grid, block>>>(mask, out);
}

// round 9
// speedup vs baseline: 1.0814x; 1.0814x over previous
#include <cuda_runtime.h>

// BinaryMaskEdgeSmoothing, R9 (= R8 resubmit; infra failure, kernel never ran):
// cp.async smem-ring pipeline.
//
// Binary inputs => sum9 (3x3 box) and gsum (16*gauss) are exact small ints in
// f32. Verified-equivalent rule (rel_err = 0.0 since R4):
//     out = (gsum >= 9) || (gsum == 8 && cen == 1 && sum9 >= 4)
// via: qual = 6*cen + sum9; adj = qual>9.5 ? 0.6 : 0; out = gsum+adj > 8.5.
//
// R7 showed register prefetch pipelines cap at ~18KB/SM in flight (regs tax
// occupancy). Here in-flight bytes live in smem instead: each block streams
// full 4KB rows through an 8-slot ring via cp.async.cg (16B/thread), lookahead
// 6 rows, one commit group per row. 4 blocks/SM x 6 rows x 4KB = 96KB/SM in
// flight with ~50 regs/thread. Consumer keeps 2 rows of horizontal sums in
// registers and reads one new row per iteration from smem.

#define IMG_W   1024
#define IMG_H   1024
#define RPB     32            // output rows per block
#define THREADS 256           // 4 cols per thread, block spans full row
#define STAGES  8             // smem ring slots (> LOOK+1)
#define LOOK    6             // cp.async lookahead (pending groups)

struct Sums { float t[4], g[4]; };   // 1,1,1 and 1,2,1 horizontal sums

__device__ __forceinline__ void cp_row16(float* dst_row, const float* src_row,
                                         int tid) {
    unsigned s = (unsigned)__cvta_generic_to_shared(dst_row + 4 * tid);
    asm volatile("cp.async.cg.shared.global [%0], [%1], 16;" ::
                 "r"(s), "l"(src_row + 4 * tid));
}
#define CP_COMMIT() asm volatile("cp.async.commit_group;")
#define CP_WAIT(n)  asm volatile("cp.async.wait_group %0;" :: "n"(n))

__device__ __forceinline__ Sums make_sums(const float* __restrict__ row,
                                          int x0) {
    float4 v = *reinterpret_cast<const float4*>(row + x0);     // LDS.128
    float l = (x0 > 0)            ? row[x0 - 1] : 0.f;         // LDS.32
    float r = (x0 + 4 < IMG_W)    ? row[x0 + 4] : 0.f;
    float e0 = l, e1 = v.x, e2 = v.y, e3 = v.z, e4 = v.w, e5 = r;
    Sums s;
    s.t[0] = e0 + e1 + e2;  s.g[0] = s.t[0] + e1;
    s.t[1] = e1 + e2 + e3;  s.g[1] = s.t[1] + e2;
    s.t[2] = e2 + e3 + e4;  s.g[2] = s.t[2] + e3;
    s.t[3] = e3 + e4 + e5;  s.g[3] = s.t[3] + e4;
    return s;
}

__device__ __forceinline__ Sums zero_sums() {
    Sums s;
    #pragma unroll
    for (int j = 0; j < 4; ++j) { s.t[j] = 0.f; s.g[j] = 0.f; }
    return s;
}

__device__ __forceinline__ float4 compute_row(const Sums& A, const Sums& B,
                                              const Sums& C) {
    float res[4];
    #pragma unroll
    for (int j = 0; j < 4; ++j) {
        float sum9 = A.t[j] + B.t[j] + C.t[j];            // 0..9 exact
        float t1   = A.g[j] + C.g[j];
        float gsum = fmaf(2.f, B.g[j], t1);               // 0..16 exact
        float cen  = B.g[j] - B.t[j];                     // 0 or 1
        float qual = fmaf(6.f, cen, sum9);                // >=10 <=> lo-qualify
        float adj  = (qual > 9.5f) ? 0.6f : 0.f;
        res[j] = (gsum + adj > 8.5f) ? 1.f : 0.f;
    }
    return make_float4(res[0], res[1], res[2], res[3]);
}

__global__ void __launch_bounds__(THREADS, 4)
edge_smooth_kernel(const float* __restrict__ in, float* __restrict__ out) {
    __shared__ float buf[STAGES][IMG_W];

    const int img = blockIdx.y;
    const int r0  = blockIdx.x * RPB;
    const int tid = threadIdx.x;
    const int x0  = tid * 4;

    const float* ibase = in  + (size_t)img * IMG_H * IMG_W;
    float*       obase = out + (size_t)img * IMG_H * IMG_W;

    // Input rows consumed: base_row + kc, kc = 0 .. RPB+1 (rows r0-1..r0+RPB).
    const int base_row = r0 - 1;
    const int KMAX = RPB + 2;

    // Prologue: issue rows kc = 0..LOOK-1 (source row clamped; out-of-range
    // rows are fetched-but-never-consumed, so clamping is safe).
    #pragma unroll
    for (int k = 0; k < LOOK; ++k) {
        int row = min(max(base_row + k, 0), IMG_H - 1);
        cp_row16(buf[k % STAGES], ibase + (size_t)row * IMG_W, tid);
        CP_COMMIT();
    }

    Sums A = zero_sums(), B = zero_sums();
    float* po = obase + (size_t)r0 * IMG_W + x0;

    for (int kc = 0; kc < KMAX; ++kc) {
        // Issue row kc+LOOK (if any); always commit so group count is uniform.
        int ki = kc + LOOK;
        if (ki < KMAX) {
            int row = min(max(base_row + ki, 0), IMG_H - 1);
            cp_row16(buf[ki % STAGES], ibase + (size_t)row * IMG_W, tid);
        }
        CP_COMMIT();
        CP_WAIT(LOOK);          // this thread's copy of row kc retired
        __syncthreads();        // neighbors' copies of row kc visible

        int row = base_row + kc;
        Sums C = (row >= 0 && row < IMG_H) ? make_sums(buf[kc % STAGES], x0)
                                           : zero_sums();
        if (kc >= 2) {
            *reinterpret_cast<float4*>(po) = compute_row(A, B, C);
            po += IMG_W;
        }
        A = B; B = C;
    }
}

extern "C" void kernel_launch(void* const* d_in, const int* in_sizes, int n_in,
                              void* d_out, int out_size) {
    const float* mask = (const float*)d_in[0];   // (B,C,1024,1024) f32
    float*       out  = (float*)d_out;

    int n_imgs = in_sizes[0] / (IMG_H * IMG_W);  // B*C

    dim3 grid(IMG_H / RPB, n_imgs);
    dim3 block(THREADS);
    edge_smooth_kernel<<<grid, block>>>(mask, out);
}